// round 7
// baseline (speedup 1.0000x reference)
#include <cuda_runtime.h>
#include <math.h>

#define T_STEPS 512
#define BATCH   64
#define IN_DIM  512
#define RNN_DIM 512

#define NCTA2   128   // 32 jblk x 4 bblk
#define NTHR2   256
#define GRP_SZ  32

typedef unsigned long long ull;

// scratch (no device allocs allowed)
__device__ float g_pre[(size_t)T_STEPS * BATCH * RNN_DIM];   // 64MB
__device__ float g_hT[2][RNN_DIM * BATCH];                    // [parity][r][b]
__device__ ull g_grp[4 * 16];                                 // group ctrs, 128B apart

// ---- f32x2 helpers (each lane is an IEEE fp32 FMA -> bit-identical) -------
__device__ __forceinline__ void ffma2(ull& d, ull a, ull b) {
    asm("fma.rn.f32x2 %0, %1, %2, %0;" : "+l"(d) : "l"(a), "l"(b));
}
__device__ __forceinline__ ull dup2(float v) {
    ull r; asm("mov.b64 %0, {%1, %1};" : "=l"(r) : "f"(v)); return r;
}
__device__ __forceinline__ float2 unpk(ull v) {
    float2 f; asm("mov.b64 {%0, %1}, %2;" : "=f"(f.x), "=f"(f.y) : "l"(v)); return f;
}

// ---------------------------------------------------------------------------
// Phase 1: pre = X @ Wx + bias. 128x128x8 tile, FFMA2 (pairs along n,
// A duplicated in smem). Block (0,0) resets phase-2 barrier state.
// ---------------------------------------------------------------------------
#define BM 128
#define BN 128
#define BK 8

__global__ __launch_bounds__(256) void gemm_pre_kernel(
    const float* __restrict__ X,
    const float* __restrict__ W,
    const float* __restrict__ bias)
{
    if (blockIdx.x == 0 && blockIdx.y == 0 && threadIdx.x < 4)
        g_grp[threadIdx.x * 16] = 0ULL;

    __shared__ float As2[BK][2 * BM];   // duplicated A, 8KB
    __shared__ float Bs[BK][BN];        // 4KB

    const int tid = threadIdx.x;
    const int bm = blockIdx.x;
    const int bn = blockIdx.y;

    const float* Aptr = X + (size_t)bm * BM * IN_DIM;
    const float* Bptr = W + (size_t)bn * BN;

    const int tm = (tid / 16) * 8;
    const int tn = (tid % 16) * 8;

    const int a_row = tid >> 1;
    const int a_kq  = (tid & 1) * 4;
    const int b_k   = tid >> 5;
    const int b_nq  = (tid & 31) * 4;

    ull c2[8][4];
    #pragma unroll
    for (int i = 0; i < 8; i++)
        #pragma unroll
        for (int j = 0; j < 4; j++)
            c2[i][j] = 0ULL;

    for (int k0 = 0; k0 < IN_DIM; k0 += BK) {
        float4 av = *(const float4*)(Aptr + (size_t)a_row * IN_DIM + k0 + a_kq);
        float4 bv = *(const float4*)(Bptr + (size_t)(k0 + b_k) * RNN_DIM + b_nq);
        __syncthreads();
        *(ull*)&As2[a_kq + 0][2 * a_row] = dup2(av.x);
        *(ull*)&As2[a_kq + 1][2 * a_row] = dup2(av.y);
        *(ull*)&As2[a_kq + 2][2 * a_row] = dup2(av.z);
        *(ull*)&As2[a_kq + 3][2 * a_row] = dup2(av.w);
        *(float4*)&Bs[b_k][b_nq] = bv;
        __syncthreads();

        #pragma unroll
        for (int k = 0; k < BK; k++) {
            ulonglong2 a01 = *(const ulonglong2*)&As2[k][2 * tm];
            ulonglong2 a23 = *(const ulonglong2*)&As2[k][2 * tm + 4];
            ulonglong2 a45 = *(const ulonglong2*)&As2[k][2 * tm + 8];
            ulonglong2 a67 = *(const ulonglong2*)&As2[k][2 * tm + 12];
            ulonglong2 b01 = *(const ulonglong2*)&Bs[k][tn];
            ulonglong2 b23 = *(const ulonglong2*)&Bs[k][tn + 4];
            ull a2[8] = {a01.x, a01.y, a23.x, a23.y, a45.x, a45.y, a67.x, a67.y};
            ull bb[4] = {b01.x, b01.y, b23.x, b23.y};
            #pragma unroll
            for (int i = 0; i < 8; i++)
                #pragma unroll
                for (int j = 0; j < 4; j++)
                    ffma2(c2[i][j], a2[i], bb[j]);
        }
    }

    float4 bb0 = *(const float4*)(bias + bn * BN + tn);
    float4 bb1 = *(const float4*)(bias + bn * BN + tn + 4);
    #pragma unroll
    for (int i = 0; i < 8; i++) {
        size_t row = (size_t)bm * BM + tm + i;
        float2 p0 = unpk(c2[i][0]), p1 = unpk(c2[i][1]);
        float2 p2 = unpk(c2[i][2]), p3 = unpk(c2[i][3]);
        float4 v0 = make_float4(p0.x + bb0.x, p0.y + bb0.y, p1.x + bb0.z, p1.y + bb0.w);
        float4 v1 = make_float4(p2.x + bb1.x, p2.y + bb1.y, p3.x + bb1.z, p3.y + bb1.w);
        *(float4*)(g_pre + row * RNN_DIM + bn * BN + tn)     = v0;
        *(float4*)(g_pre + row * RNN_DIM + bn * BN + tn + 4) = v1;
    }
}

// ---------------------------------------------------------------------------
// Phase 2: persistent RNN (R4 structure), FFMA2 compute (pairs along b,
// Wh duplicated in smem once).
// ---------------------------------------------------------------------------
__device__ __forceinline__ void group_barrier(int grp, ull step)
{
    __syncthreads();
    if (threadIdx.x == 0) {
        __threadfence();
        atomicAdd(&g_grp[grp * 16], 1ULL);     // no-return -> REDG
        volatile ull* ctr = (volatile ull*)&g_grp[grp * 16];
        ull need = (ull)GRP_SZ * step;
        while (*ctr < need) { }
        __threadfence();
    }
    __syncthreads();
}

extern __shared__ float smem2[];

__global__ __launch_bounds__(NTHR2) void rnn_seq_kernel(
    const float* __restrict__ W,
    const float* __restrict__ init_hidden,
    float* __restrict__ out)
{
    float* ws2 = smem2;                  // [512][32] duplicated Wh slice, 64KB
    float* hs  = smem2 + RNN_DIM * 32;   // [512][16] h slab, 32KB (rows<256 = red)

    const int tid  = threadIdx.x;
    const int jblk = blockIdx.x & 31;
    const int bblk = blockIdx.x >> 5;
    const int j0 = jblk * 16;
    const int b0 = bblk * 16;

    // Wh slice, duplicated along j: ws2[r][2j]=ws2[r][2j+1]=Wh[r][j0+j]
    #pragma unroll
    for (int i = 0; i < 8; i++) {
        int idx = tid + i * NTHR2;
        int r = idx >> 2, q = (idx & 3) * 4;
        float4 v = *(const float4*)(W + (size_t)(IN_DIM + r) * RNN_DIM + j0 + q);
        *(ull*)&ws2[r * 32 + 2 * q + 0] = dup2(v.x);
        *(ull*)&ws2[r * 32 + 2 * q + 2] = dup2(v.y);
        *(ull*)&ws2[r * 32 + 2 * q + 4] = dup2(v.z);
        *(ull*)&ws2[r * 32 + 2 * q + 6] = dup2(v.w);
    }

    // out[0] tile = broadcast init_hidden
    {
        int b = tid >> 4, j = tid & 15;
        out[(size_t)(b0 + b) * RNN_DIM + j0 + j] = init_hidden[j0 + j];
    }
    // g_hT[0][r][b0..b0+15] = init_hidden[r]  (one CTA per group: jblk==0)
    if (jblk == 0) {
        int kbase = (tid >> 2) * 8;
        int q = (tid & 3) * 4;
        #pragma unroll
        for (int kk = 0; kk < 8; kk++) {
            int k = kbase + kk;
            float v = init_hidden[k];
            *(float4*)&g_hT[0][k * BATCH + b0 + q] = make_float4(v, v, v, v);
        }
    }
    group_barrier(bblk, 1ULL);

    const int kg = tid >> 4;              // 0..15, k = kg + 16*kk (strided)
    const int tt = tid & 15;
    const int bq = (tt >> 2) * 4;         // 0,4,8,12
    const int jq = (tt & 3) * 4;          // 0,4,8,12
    const int fb = tid >> 4;              // epilogue b
    const int fj = tid & 15;              // epilogue j

    for (int t = 0; t < T_STEPS - 1; t++) {
        const float* hsrc = g_hT[t & 1];

        // stage half0 (rows 0..255)
        float4 r0[4];
        #pragma unroll
        for (int i = 0; i < 4; i++) {
            int idx = tid + i * NTHR2;
            int r = idx >> 2, q = (idx & 3) * 4;
            r0[i] = *(const float4*)(hsrc + r * BATCH + b0 + q);
        }
        float pre = g_pre[((size_t)t * BATCH + b0 + fb) * RNN_DIM + j0 + fj];
        #pragma unroll
        for (int i = 0; i < 4; i++) {
            int idx = tid + i * NTHR2;
            int r = idx >> 2, q = (idx & 3) * 4;
            *(float4*)&hs[r * 16 + q] = r0[i];
        }
        __syncthreads();

        // issue half1 loads (rows 256..511), overlap with compute half0
        float4 r1[4];
        #pragma unroll
        for (int i = 0; i < 4; i++) {
            int idx = tid + (i + 4) * NTHR2;
            int r = idx >> 2, q = (idx & 3) * 4;
            r1[i] = *(const float4*)(hsrc + r * BATCH + b0 + q);
        }

        ull c2[2][4];
        #pragma unroll
        for (int p = 0; p < 2; p++)
            #pragma unroll
            for (int j = 0; j < 4; j++)
                c2[p][j] = 0ULL;

        #pragma unroll 8
        for (int kk = 0; kk < 16; kk++) {       // k in [0,256)
            int k = kg + (kk << 4);
            ulonglong2 hp  = *(const ulonglong2*)&hs[k * 16 + bq];
            ulonglong2 w01 = *(const ulonglong2*)&ws2[k * 32 + 2 * jq];
            ulonglong2 w23 = *(const ulonglong2*)&ws2[k * 32 + 2 * jq + 4];
            ffma2(c2[0][0], hp.x, w01.x); ffma2(c2[0][1], hp.x, w01.y);
            ffma2(c2[0][2], hp.x, w23.x); ffma2(c2[0][3], hp.x, w23.y);
            ffma2(c2[1][0], hp.y, w01.x); ffma2(c2[1][1], hp.y, w01.y);
            ffma2(c2[1][2], hp.y, w23.x); ffma2(c2[1][3], hp.y, w23.y);
        }

        #pragma unroll
        for (int i = 0; i < 4; i++) {
            int idx = tid + (i + 4) * NTHR2;
            int r = idx >> 2, q = (idx & 3) * 4;
            *(float4*)&hs[r * 16 + q] = r1[i];
        }
        __syncthreads();

        #pragma unroll 8
        for (int kk = 16; kk < 32; kk++) {      // k in [256,512)
            int k = kg + (kk << 4);
            ulonglong2 hp  = *(const ulonglong2*)&hs[k * 16 + bq];
            ulonglong2 w01 = *(const ulonglong2*)&ws2[k * 32 + 2 * jq];
            ulonglong2 w23 = *(const ulonglong2*)&ws2[k * 32 + 2 * jq + 4];
            ffma2(c2[0][0], hp.x, w01.x); ffma2(c2[0][1], hp.x, w01.y);
            ffma2(c2[0][2], hp.x, w23.x); ffma2(c2[0][3], hp.x, w23.y);
            ffma2(c2[1][0], hp.y, w01.x); ffma2(c2[1][1], hp.y, w01.y);
            ffma2(c2[1][2], hp.y, w23.x); ffma2(c2[1][3], hp.y, w23.y);
        }

        // k-split partials overlay hs rows < 256 (safe: half1 reads rows >= 256)
        // hp.x = (h[bq],h[bq+1]) -> c2[p][j] lanes are b = bq+2p (+1), col jq+j
        float* red = hs;
        #pragma unroll
        for (int p = 0; p < 2; p++)
            #pragma unroll
            for (int j = 0; j < 4; j++) {
                float2 f = unpk(c2[p][j]);
                red[kg * 256 + (bq + 2 * p + 0) * 16 + jq + j] = f.x;
                red[kg * 256 + (bq + 2 * p + 1) * 16 + jq + j] = f.y;
            }
        __syncthreads();

        float s = 0.0f;
        #pragma unroll
        for (int g = 0; g < 16; g++)
            s += red[g * 256 + tid];            // tid == b*16+j, conflict-free
        float h = tanhf(s + pre);
        out[((size_t)(t + 1) * BATCH + b0 + fb) * RNN_DIM + j0 + fj] = h;
        g_hT[(t + 1) & 1][(j0 + fj) * BATCH + b0 + fb] = h;

        if (t < T_STEPS - 2)
            group_barrier(bblk, (ull)(t + 2));
    }
}

// ---------------------------------------------------------------------------
extern "C" void kernel_launch(void* const* d_in, const int* in_sizes, int n_in,
                              void* d_out, int out_size)
{
    const float* X    = (const float*)d_in[0];  // [T, B, IN_DIM]
    const float* W    = (const float*)d_in[1];  // [IN_DIM + RNN_DIM, RNN_DIM]
    const float* bias = (const float*)d_in[2];  // [RNN_DIM]
    const float* h0   = (const float*)d_in[3];  // [RNN_DIM]
    float* out = (float*)d_out;                 // [T, B, RNN_DIM]

    cudaFuncSetAttribute(rnn_seq_kernel,
                         cudaFuncAttributeMaxDynamicSharedMemorySize, 98304);

    dim3 g1((T_STEPS * BATCH) / BM, RNN_DIM / BN);  // (256, 4)
    gemm_pre_kernel<<<g1, 256>>>(X, W, bias);

    rnn_seq_kernel<<<NCTA2, NTHR2, 98304>>>(W, h0, out);
}

// round 8
// speedup vs baseline: 1.0568x; 1.0568x over previous
#include <cuda_runtime.h>
#include <math.h>

#define T_STEPS 512
#define BATCH   64
#define IN_DIM  512
#define RNN_DIM 512

#define NCTA2   128   // 32 jblk x 4 bblk
#define NTHR2   512   // 16 warps
#define GRP_SZ  32

typedef unsigned long long ull;

// scratch (no device allocs allowed)
__device__ float g_pre[(size_t)T_STEPS * BATCH * RNN_DIM];   // 64MB
__device__ float g_hT[2][RNN_DIM * BATCH];                    // [parity][r][b]
__device__ ull g_grp[4 * 16];                                 // group ctrs, 128B apart

// ---- f32x2 helpers (each lane is an IEEE fp32 FMA -> bit-identical) -------
__device__ __forceinline__ void ffma2(ull& d, ull a, ull b) {
    asm("fma.rn.f32x2 %0, %1, %2, %0;" : "+l"(d) : "l"(a), "l"(b));
}
__device__ __forceinline__ ull dup2(float v) {
    ull r; asm("mov.b64 %0, {%1, %1};" : "=l"(r) : "f"(v)); return r;
}
__device__ __forceinline__ float2 unpk(ull v) {
    float2 f; asm("mov.b64 {%0, %1}, %2;" : "=f"(f.x), "=f"(f.y) : "l"(v)); return f;
}

// ---------------------------------------------------------------------------
// Phase 1: pre = X @ Wx + bias. 128x128x8 tile, FFMA2 (pairs along n,
// A duplicated in smem). Block (0,0) resets phase-2 barrier state.
// ---------------------------------------------------------------------------
#define BM 128
#define BN 128
#define BK 8

__global__ __launch_bounds__(256) void gemm_pre_kernel(
    const float* __restrict__ X,
    const float* __restrict__ W,
    const float* __restrict__ bias)
{
    if (blockIdx.x == 0 && blockIdx.y == 0 && threadIdx.x < 4)
        g_grp[threadIdx.x * 16] = 0ULL;

    __shared__ float As2[BK][2 * BM];   // duplicated A, 8KB
    __shared__ float Bs[BK][BN];        // 4KB

    const int tid = threadIdx.x;
    const int bm = blockIdx.x;
    const int bn = blockIdx.y;

    const float* Aptr = X + (size_t)bm * BM * IN_DIM;
    const float* Bptr = W + (size_t)bn * BN;

    const int tm = (tid / 16) * 8;
    const int tn = (tid % 16) * 8;

    const int a_row = tid >> 1;
    const int a_kq  = (tid & 1) * 4;
    const int b_k   = tid >> 5;
    const int b_nq  = (tid & 31) * 4;

    ull c2[8][4];
    #pragma unroll
    for (int i = 0; i < 8; i++)
        #pragma unroll
        for (int j = 0; j < 4; j++)
            c2[i][j] = 0ULL;

    for (int k0 = 0; k0 < IN_DIM; k0 += BK) {
        float4 av = *(const float4*)(Aptr + (size_t)a_row * IN_DIM + k0 + a_kq);
        float4 bv = *(const float4*)(Bptr + (size_t)(k0 + b_k) * RNN_DIM + b_nq);
        __syncthreads();
        *(ull*)&As2[a_kq + 0][2 * a_row] = dup2(av.x);
        *(ull*)&As2[a_kq + 1][2 * a_row] = dup2(av.y);
        *(ull*)&As2[a_kq + 2][2 * a_row] = dup2(av.z);
        *(ull*)&As2[a_kq + 3][2 * a_row] = dup2(av.w);
        *(float4*)&Bs[b_k][b_nq] = bv;
        __syncthreads();

        #pragma unroll
        for (int k = 0; k < BK; k++) {
            ulonglong2 a01 = *(const ulonglong2*)&As2[k][2 * tm];
            ulonglong2 a23 = *(const ulonglong2*)&As2[k][2 * tm + 4];
            ulonglong2 a45 = *(const ulonglong2*)&As2[k][2 * tm + 8];
            ulonglong2 a67 = *(const ulonglong2*)&As2[k][2 * tm + 12];
            ulonglong2 b01 = *(const ulonglong2*)&Bs[k][tn];
            ulonglong2 b23 = *(const ulonglong2*)&Bs[k][tn + 4];
            ull a2[8] = {a01.x, a01.y, a23.x, a23.y, a45.x, a45.y, a67.x, a67.y};
            ull bb[4] = {b01.x, b01.y, b23.x, b23.y};
            #pragma unroll
            for (int i = 0; i < 8; i++)
                #pragma unroll
                for (int j = 0; j < 4; j++)
                    ffma2(c2[i][j], a2[i], bb[j]);
        }
    }

    float4 bb0 = *(const float4*)(bias + bn * BN + tn);
    float4 bb1 = *(const float4*)(bias + bn * BN + tn + 4);
    #pragma unroll
    for (int i = 0; i < 8; i++) {
        size_t row = (size_t)bm * BM + tm + i;
        float2 p0 = unpk(c2[i][0]), p1 = unpk(c2[i][1]);
        float2 p2 = unpk(c2[i][2]), p3 = unpk(c2[i][3]);
        float4 v0 = make_float4(p0.x + bb0.x, p0.y + bb0.y, p1.x + bb0.z, p1.y + bb0.w);
        float4 v1 = make_float4(p2.x + bb1.x, p2.y + bb1.y, p3.x + bb1.z, p3.y + bb1.w);
        *(float4*)(g_pre + row * RNN_DIM + bn * BN + tn)     = v0;
        *(float4*)(g_pre + row * RNN_DIM + bn * BN + tn + 4) = v1;
    }
}

// ---------------------------------------------------------------------------
// Phase 2: persistent RNN, R4 math, 512 threads, split arrive/wait barrier.
// ---------------------------------------------------------------------------
__device__ __forceinline__ void group_arrive(int grp)
{
    __syncthreads();                     // all g_hT stores issued
    if (threadIdx.x == 0) {
        __threadfence();
        atomicAdd(&g_grp[grp * 16], 1ULL);   // no-return -> REDG
    }
}
__device__ __forceinline__ void group_wait(int grp, ull step)
{
    if (threadIdx.x == 0) {
        volatile ull* ctr = (volatile ull*)&g_grp[grp * 16];
        ull need = (ull)GRP_SZ * step;
        while (*ctr < need) { }
        __threadfence();
    }
    __syncthreads();
}

extern __shared__ float smem2[];

__global__ __launch_bounds__(NTHR2) void rnn_seq_kernel(
    const float* __restrict__ W,
    const float* __restrict__ init_hidden,
    float* __restrict__ out)
{
    float* ws = smem2;                 // [512][16] Wh slice, 32KB
    float* hs = smem2 + RNN_DIM * 16;  // [512][16] h slab, 32KB (full overlay = red[32][256])

    const int tid  = threadIdx.x;
    const int jblk = blockIdx.x & 31;
    const int bblk = blockIdx.x >> 5;
    const int j0 = jblk * 16;
    const int b0 = bblk * 16;

    // Wh slice (rows 512..1023 of W, cols j0..j0+15), loaded once
    #pragma unroll
    for (int i = 0; i < 4; i++) {
        int idx = tid + i * NTHR2;
        int r = idx >> 2, q = (idx & 3) * 4;
        *(float4*)&ws[r * 16 + q] =
            *(const float4*)(W + (size_t)(IN_DIM + r) * RNN_DIM + j0 + q);
    }

    // out[0] tile = broadcast init_hidden
    if (tid < 256) {
        int b = tid >> 4, j = tid & 15;
        out[(size_t)(b0 + b) * RNN_DIM + j0 + j] = init_hidden[j0 + j];
    }
    // g_hT[0][r][b0..b0+15] = init_hidden[r]  (one CTA per group: jblk==0)
    if (jblk == 0) {
        #pragma unroll
        for (int i = 0; i < 4; i++) {
            int idx = tid + i * NTHR2;
            int r = idx >> 2, q = (idx & 3) * 4;
            float v = init_hidden[r];
            *(float4*)&g_hT[0][r * BATCH + b0 + q] = make_float4(v, v, v, v);
        }
    }
    group_arrive(bblk);
    group_wait(bblk, 1ULL);

    const int kg = tid >> 4;              // 0..31, k = kg + 32*kk (strided)
    const int tt = tid & 15;
    const int bq = (tt >> 2) * 4;         // 0,4,8,12
    const int jq = (tt & 3) * 4;          // 0,4,8,12
    const int fb = tid >> 4;              // epilogue b (tid<256)
    const int fj = tid & 15;              // epilogue j

    for (int t = 0; t < T_STEPS - 1; t++) {
        const float* hsrc = g_hT[t & 1];

        // stage half0 (rows 0..255): 1024 float4 by 512 threads
        float4 r0[2];
        #pragma unroll
        for (int i = 0; i < 2; i++) {
            int idx = tid + i * NTHR2;
            int r = idx >> 2, q = (idx & 3) * 4;
            r0[i] = *(const float4*)(hsrc + r * BATCH + b0 + q);
        }
        float pre = 0.0f;
        if (tid < 256)
            pre = g_pre[((size_t)t * BATCH + b0 + fb) * RNN_DIM + j0 + fj];
        #pragma unroll
        for (int i = 0; i < 2; i++) {
            int idx = tid + i * NTHR2;
            int r = idx >> 2, q = (idx & 3) * 4;
            *(float4*)&hs[r * 16 + q] = r0[i];
        }
        __syncthreads();

        // issue half1 loads (rows 256..511), overlap with compute half0
        float4 r1[2];
        #pragma unroll
        for (int i = 0; i < 2; i++) {
            int idx = tid + (i + 2) * NTHR2;
            int r = idx >> 2, q = (idx & 3) * 4;
            r1[i] = *(const float4*)(hsrc + r * BATCH + b0 + q);
        }

        float c[4][4];
        #pragma unroll
        for (int i = 0; i < 4; i++)
            #pragma unroll
            for (int j = 0; j < 4; j++)
                c[i][j] = 0.0f;

        #pragma unroll
        for (int kk = 0; kk < 8; kk++) {        // k in [0,256)
            int k = kg + (kk << 5);
            float4 hv = *(float4*)&hs[k * 16 + bq];
            float4 wv = *(float4*)&ws[k * 16 + jq];
            c[0][0] += hv.x * wv.x; c[0][1] += hv.x * wv.y;
            c[0][2] += hv.x * wv.z; c[0][3] += hv.x * wv.w;
            c[1][0] += hv.y * wv.x; c[1][1] += hv.y * wv.y;
            c[1][2] += hv.y * wv.z; c[1][3] += hv.y * wv.w;
            c[2][0] += hv.z * wv.x; c[2][1] += hv.z * wv.y;
            c[2][2] += hv.z * wv.z; c[2][3] += hv.z * wv.w;
            c[3][0] += hv.w * wv.x; c[3][1] += hv.w * wv.y;
            c[3][2] += hv.w * wv.z; c[3][3] += hv.w * wv.w;
        }

        #pragma unroll
        for (int i = 0; i < 2; i++) {
            int idx = tid + (i + 2) * NTHR2;
            int r = idx >> 2, q = (idx & 3) * 4;
            *(float4*)&hs[r * 16 + q] = r1[i];
        }
        __syncthreads();

        #pragma unroll
        for (int kk = 8; kk < 16; kk++) {       // k in [256,512)
            int k = kg + (kk << 5);
            float4 hv = *(float4*)&hs[k * 16 + bq];
            float4 wv = *(float4*)&ws[k * 16 + jq];
            c[0][0] += hv.x * wv.x; c[0][1] += hv.x * wv.y;
            c[0][2] += hv.x * wv.z; c[0][3] += hv.x * wv.w;
            c[1][0] += hv.y * wv.x; c[1][1] += hv.y * wv.y;
            c[1][2] += hv.y * wv.z; c[1][3] += hv.y * wv.w;
            c[2][0] += hv.z * wv.x; c[2][1] += hv.z * wv.y;
            c[2][2] += hv.z * wv.z; c[2][3] += hv.z * wv.w;
            c[3][0] += hv.w * wv.x; c[3][1] += hv.w * wv.y;
            c[3][2] += hv.w * wv.z; c[3][3] += hv.w * wv.w;
        }
        __syncthreads();                        // all done reading hs

        // k-split partials: red[32][256] = full hs overlay (32KB)
        float* red = hs;
        #pragma unroll
        for (int i = 0; i < 4; i++)
            #pragma unroll
            for (int j = 0; j < 4; j++)
                red[kg * 256 + (bq + i) * 16 + (jq + j)] = c[i][j];
        __syncthreads();

        float h = 0.0f;
        if (tid < 256) {
            float s = 0.0f;
            #pragma unroll
            for (int g = 0; g < 32; g++)
                s += red[g * 256 + tid];        // tid == b*16+j, conflict-free
            h = tanhf(s + pre);
            g_hT[(t + 1) & 1][(j0 + fj) * BATCH + b0 + fb] = h;
        }

        if (t < T_STEPS - 2) {
            group_arrive(bblk);                 // publish ASAP
            if (tid < 256)                      // out store off the critical path
                out[((size_t)(t + 1) * BATCH + b0 + fb) * RNN_DIM + j0 + fj] = h;
            group_wait(bblk, (ull)(t + 2));
        } else {
            if (tid < 256)
                out[((size_t)(t + 1) * BATCH + b0 + fb) * RNN_DIM + j0 + fj] = h;
        }
    }
}

// ---------------------------------------------------------------------------
extern "C" void kernel_launch(void* const* d_in, const int* in_sizes, int n_in,
                              void* d_out, int out_size)
{
    const float* X    = (const float*)d_in[0];  // [T, B, IN_DIM]
    const float* W    = (const float*)d_in[1];  // [IN_DIM + RNN_DIM, RNN_DIM]
    const float* bias = (const float*)d_in[2];  // [RNN_DIM]
    const float* h0   = (const float*)d_in[3];  // [RNN_DIM]
    float* out = (float*)d_out;                 // [T, B, RNN_DIM]

    cudaFuncSetAttribute(rnn_seq_kernel,
                         cudaFuncAttributeMaxDynamicSharedMemorySize, 65536);

    dim3 g1((T_STEPS * BATCH) / BM, RNN_DIM / BN);  // (256, 4)
    gemm_pre_kernel<<<g1, 256>>>(X, W, bias);

    rnn_seq_kernel<<<NCTA2, NTHR2, 65536>>>(W, h0, out);
}

// round 9
// speedup vs baseline: 1.0678x; 1.0104x over previous
#include <cuda_runtime.h>
#include <math.h>

#define T_STEPS 512
#define BATCH   64
#define IN_DIM  512
#define RNN_DIM 512

#define NCTA2   128   // 32 jblk x 4 bblk
#define NTHR2   256
#define GRP_SZ  32

typedef unsigned long long ull;

// scratch (no device allocs allowed)
__device__ float g_pre[(size_t)T_STEPS * BATCH * RNN_DIM];   // 64MB
__device__ float g_hT[2][RNN_DIM * BATCH];                    // [parity][r][b]
__device__ ull g_grp[4 * 16];                                 // group ctrs, 128B apart

// ---- f32x2 helpers (each lane is an IEEE fp32 FMA -> bit-identical) -------
__device__ __forceinline__ void ffma2(ull& d, ull a, ull b) {
    asm("fma.rn.f32x2 %0, %1, %2, %0;" : "+l"(d) : "l"(a), "l"(b));
}
__device__ __forceinline__ ull dup2(float v) {
    ull r; asm("mov.b64 %0, {%1, %1};" : "=l"(r) : "f"(v)); return r;
}
__device__ __forceinline__ float2 unpk(ull v) {
    float2 f; asm("mov.b64 {%0, %1}, %2;" : "=f"(f.x), "=f"(f.y) : "l"(v)); return f;
}

// ---------------------------------------------------------------------------
// Phase 1: pre = X @ Wx + bias. 128x128x8 tile, FFMA2 (pairs along n,
// A duplicated in smem). Block (0,0) resets phase-2 barrier state.
// ---------------------------------------------------------------------------
#define BM 128
#define BN 128
#define BK 8

__global__ __launch_bounds__(256) void gemm_pre_kernel(
    const float* __restrict__ X,
    const float* __restrict__ W,
    const float* __restrict__ bias)
{
    if (blockIdx.x == 0 && blockIdx.y == 0 && threadIdx.x < 4)
        g_grp[threadIdx.x * 16] = 0ULL;

    __shared__ float As2[BK][2 * BM];   // duplicated A, 8KB
    __shared__ float Bs[BK][BN];        // 4KB

    const int tid = threadIdx.x;
    const int bm = blockIdx.x;
    const int bn = blockIdx.y;

    const float* Aptr = X + (size_t)bm * BM * IN_DIM;
    const float* Bptr = W + (size_t)bn * BN;

    const int tm = (tid / 16) * 8;
    const int tn = (tid % 16) * 8;

    const int a_row = tid >> 1;
    const int a_kq  = (tid & 1) * 4;
    const int b_k   = tid >> 5;
    const int b_nq  = (tid & 31) * 4;

    ull c2[8][4];
    #pragma unroll
    for (int i = 0; i < 8; i++)
        #pragma unroll
        for (int j = 0; j < 4; j++)
            c2[i][j] = 0ULL;

    for (int k0 = 0; k0 < IN_DIM; k0 += BK) {
        float4 av = *(const float4*)(Aptr + (size_t)a_row * IN_DIM + k0 + a_kq);
        float4 bv = *(const float4*)(Bptr + (size_t)(k0 + b_k) * RNN_DIM + b_nq);
        __syncthreads();
        *(ull*)&As2[a_kq + 0][2 * a_row] = dup2(av.x);
        *(ull*)&As2[a_kq + 1][2 * a_row] = dup2(av.y);
        *(ull*)&As2[a_kq + 2][2 * a_row] = dup2(av.z);
        *(ull*)&As2[a_kq + 3][2 * a_row] = dup2(av.w);
        *(float4*)&Bs[b_k][b_nq] = bv;
        __syncthreads();

        #pragma unroll
        for (int k = 0; k < BK; k++) {
            ulonglong2 a01 = *(const ulonglong2*)&As2[k][2 * tm];
            ulonglong2 a23 = *(const ulonglong2*)&As2[k][2 * tm + 4];
            ulonglong2 a45 = *(const ulonglong2*)&As2[k][2 * tm + 8];
            ulonglong2 a67 = *(const ulonglong2*)&As2[k][2 * tm + 12];
            ulonglong2 b01 = *(const ulonglong2*)&Bs[k][tn];
            ulonglong2 b23 = *(const ulonglong2*)&Bs[k][tn + 4];
            ull a2[8] = {a01.x, a01.y, a23.x, a23.y, a45.x, a45.y, a67.x, a67.y};
            ull bb[4] = {b01.x, b01.y, b23.x, b23.y};
            #pragma unroll
            for (int i = 0; i < 8; i++)
                #pragma unroll
                for (int j = 0; j < 4; j++)
                    ffma2(c2[i][j], a2[i], bb[j]);
        }
    }

    float4 bb0 = *(const float4*)(bias + bn * BN + tn);
    float4 bb1 = *(const float4*)(bias + bn * BN + tn + 4);
    #pragma unroll
    for (int i = 0; i < 8; i++) {
        size_t row = (size_t)bm * BM + tm + i;
        float2 p0 = unpk(c2[i][0]), p1 = unpk(c2[i][1]);
        float2 p2 = unpk(c2[i][2]), p3 = unpk(c2[i][3]);
        float4 v0 = make_float4(p0.x + bb0.x, p0.y + bb0.y, p1.x + bb0.z, p1.y + bb0.w);
        float4 v1 = make_float4(p2.x + bb1.x, p2.y + bb1.y, p3.x + bb1.z, p3.y + bb1.w);
        *(float4*)(g_pre + row * RNN_DIM + bn * BN + tn)     = v0;
        *(float4*)(g_pre + row * RNN_DIM + bn * BN + tn + 4) = v1;
    }
}

// ---------------------------------------------------------------------------
// Phase 2: persistent RNN — R4 structure byte-for-byte, plus:
//  - split arrive/wait barrier (out-store between them)
//  - pre[t+1] prefetched during the barrier wait
// ---------------------------------------------------------------------------
__device__ __forceinline__ void group_arrive(int grp)
{
    __syncthreads();                     // all g_hT stores issued
    if (threadIdx.x == 0) {
        __threadfence();
        atomicAdd(&g_grp[grp * 16], 1ULL);   // no-return -> REDG
    }
}
__device__ __forceinline__ void group_wait(int grp, ull step)
{
    if (threadIdx.x == 0) {
        volatile ull* ctr = (volatile ull*)&g_grp[grp * 16];
        ull need = (ull)GRP_SZ * step;
        while (*ctr < need) { }
        __threadfence();
    }
    __syncthreads();
}

extern __shared__ float smem2[];

__global__ __launch_bounds__(NTHR2) void rnn_seq_kernel(
    const float* __restrict__ W,
    const float* __restrict__ init_hidden,
    float* __restrict__ out)
{
    float* ws = smem2;                 // [512][16] Wh slice, 32KB
    float* hs = smem2 + RNN_DIM * 16;  // [512][16] h slab, 32KB (rows<256 = red)

    const int tid  = threadIdx.x;
    const int jblk = blockIdx.x & 31;
    const int bblk = blockIdx.x >> 5;
    const int j0 = jblk * 16;
    const int b0 = bblk * 16;

    // Wh slice (rows 512..1023 of W, cols j0..j0+15), loaded once
    #pragma unroll
    for (int i = 0; i < 8; i++) {
        int idx = tid + i * NTHR2;
        int r = idx >> 2, q = (idx & 3) * 4;
        *(float4*)&ws[r * 16 + q] =
            *(const float4*)(W + (size_t)(IN_DIM + r) * RNN_DIM + j0 + q);
    }

    // out[0] tile = broadcast init_hidden
    {
        int b = tid >> 4, j = tid & 15;
        out[(size_t)(b0 + b) * RNN_DIM + j0 + j] = init_hidden[j0 + j];
    }
    // g_hT[0][r][b0..b0+15] = init_hidden[r]  (one CTA per group: jblk==0)
    if (jblk == 0) {
        int kbase = (tid >> 2) * 8;
        int q = (tid & 3) * 4;
        #pragma unroll
        for (int kk = 0; kk < 8; kk++) {
            int k = kbase + kk;
            float v = init_hidden[k];
            *(float4*)&g_hT[0][k * BATCH + b0 + q] = make_float4(v, v, v, v);
        }
    }
    group_arrive(bblk);

    const int kg = tid >> 4;              // 0..15, k = kg + 16*kk (strided)
    const int tt = tid & 15;
    const int bq = (tt >> 2) * 4;         // 0,4,8,12
    const int jq = (tt & 3) * 4;          // 0,4,8,12
    const int fb = tid >> 4;              // epilogue b
    const int fj = tid & 15;              // epilogue j

    // prefetch pre[0] while waiting for h(0) publication
    float pre = g_pre[((size_t)0 * BATCH + b0 + fb) * RNN_DIM + j0 + fj];
    group_wait(bblk, 1ULL);

    for (int t = 0; t < T_STEPS - 1; t++) {
        const float* hsrc = g_hT[t & 1];

        // stage half0 (rows 0..255)
        float4 r0[4];
        #pragma unroll
        for (int i = 0; i < 4; i++) {
            int idx = tid + i * NTHR2;
            int r = idx >> 2, q = (idx & 3) * 4;
            r0[i] = *(const float4*)(hsrc + r * BATCH + b0 + q);
        }
        #pragma unroll
        for (int i = 0; i < 4; i++) {
            int idx = tid + i * NTHR2;
            int r = idx >> 2, q = (idx & 3) * 4;
            *(float4*)&hs[r * 16 + q] = r0[i];
        }
        __syncthreads();

        // issue half1 loads (rows 256..511), overlap with compute half0
        float4 r1[4];
        #pragma unroll
        for (int i = 0; i < 4; i++) {
            int idx = tid + (i + 4) * NTHR2;
            int r = idx >> 2, q = (idx & 3) * 4;
            r1[i] = *(const float4*)(hsrc + r * BATCH + b0 + q);
        }

        float c[4][4];
        #pragma unroll
        for (int i = 0; i < 4; i++)
            #pragma unroll
            for (int j = 0; j < 4; j++)
                c[i][j] = 0.0f;

        #pragma unroll 4
        for (int kk = 0; kk < 16; kk++) {       // k in [0,256)
            int k = kg + (kk << 4);
            float4 hv = *(float4*)&hs[k * 16 + bq];
            float4 wv = *(float4*)&ws[k * 16 + jq];
            c[0][0] += hv.x * wv.x; c[0][1] += hv.x * wv.y;
            c[0][2] += hv.x * wv.z; c[0][3] += hv.x * wv.w;
            c[1][0] += hv.y * wv.x; c[1][1] += hv.y * wv.y;
            c[1][2] += hv.y * wv.z; c[1][3] += hv.y * wv.w;
            c[2][0] += hv.z * wv.x; c[2][1] += hv.z * wv.y;
            c[2][2] += hv.z * wv.z; c[2][3] += hv.z * wv.w;
            c[3][0] += hv.w * wv.x; c[3][1] += hv.w * wv.y;
            c[3][2] += hv.w * wv.z; c[3][3] += hv.w * wv.w;
        }

        #pragma unroll
        for (int i = 0; i < 4; i++) {
            int idx = tid + (i + 4) * NTHR2;
            int r = idx >> 2, q = (idx & 3) * 4;
            *(float4*)&hs[r * 16 + q] = r1[i];
        }
        __syncthreads();

        #pragma unroll 4
        for (int kk = 16; kk < 32; kk++) {      // k in [256,512)
            int k = kg + (kk << 4);
            float4 hv = *(float4*)&hs[k * 16 + bq];
            float4 wv = *(float4*)&ws[k * 16 + jq];
            c[0][0] += hv.x * wv.x; c[0][1] += hv.x * wv.y;
            c[0][2] += hv.x * wv.z; c[0][3] += hv.x * wv.w;
            c[1][0] += hv.y * wv.x; c[1][1] += hv.y * wv.y;
            c[1][2] += hv.y * wv.z; c[1][3] += hv.y * wv.w;
            c[2][0] += hv.z * wv.x; c[2][1] += hv.z * wv.y;
            c[2][2] += hv.z * wv.z; c[2][3] += hv.z * wv.w;
            c[3][0] += hv.w * wv.x; c[3][1] += hv.w * wv.y;
            c[3][2] += hv.w * wv.z; c[3][3] += hv.w * wv.w;
        }

        // k-split partials overlay hs rows < 256 (safe: half1 reads rows >= 256)
        float* red = hs;
        #pragma unroll
        for (int i = 0; i < 4; i++)
            #pragma unroll
            for (int j = 0; j < 4; j++)
                red[kg * 256 + (bq + i) * 16 + (jq + j)] = c[i][j];
        __syncthreads();

        float s = 0.0f;
        #pragma unroll
        for (int g = 0; g < 16; g++)
            s += red[g * 256 + tid];            // tid == b*16+j, conflict-free
        float h = tanhf(s + pre);
        g_hT[(t + 1) & 1][(j0 + fj) * BATCH + b0 + fb] = h;

        if (t < T_STEPS - 2) {
            group_arrive(bblk);                 // publish ASAP
            // off-critical-path work under the barrier wait:
            out[((size_t)(t + 1) * BATCH + b0 + fb) * RNN_DIM + j0 + fj] = h;
            pre = g_pre[((size_t)(t + 1) * BATCH + b0 + fb) * RNN_DIM + j0 + fj];
            group_wait(bblk, (ull)(t + 2));
        } else {
            out[((size_t)(t + 1) * BATCH + b0 + fb) * RNN_DIM + j0 + fj] = h;
        }
    }
}

// ---------------------------------------------------------------------------
extern "C" void kernel_launch(void* const* d_in, const int* in_sizes, int n_in,
                              void* d_out, int out_size)
{
    const float* X    = (const float*)d_in[0];  // [T, B, IN_DIM]
    const float* W    = (const float*)d_in[1];  // [IN_DIM + RNN_DIM, RNN_DIM]
    const float* bias = (const float*)d_in[2];  // [RNN_DIM]
    const float* h0   = (const float*)d_in[3];  // [RNN_DIM]
    float* out = (float*)d_out;                 // [T, B, RNN_DIM]

    cudaFuncSetAttribute(rnn_seq_kernel,
                         cudaFuncAttributeMaxDynamicSharedMemorySize, 65536);

    dim3 g1((T_STEPS * BATCH) / BM, RNN_DIM / BN);  // (256, 4)
    gemm_pre_kernel<<<g1, 256>>>(X, W, bias);

    rnn_seq_kernel<<<NCTA2, NTHR2, 65536>>>(W, h0, out);
}

// round 10
// speedup vs baseline: 1.1214x; 1.0502x over previous
#include <cuda_runtime.h>
#include <math.h>

#define T_STEPS 512
#define BATCH   64
#define IN_DIM  512
#define RNN_DIM 512

#define NCTA2   128   // 32 jblk x 4 bblk
#define NTHR2   256
#define GRP_SZ  32

typedef unsigned long long ull;

// scratch (no device allocs allowed)
__device__ float g_pre[(size_t)T_STEPS * BATCH * RNN_DIM];   // 64MB
__device__ float g_hT[2][RNN_DIM * BATCH];                    // [parity][r][b]
__device__ ull g_grp[4 * 16];                                 // group ctrs, 128B apart

// ---------------------------------------------------------------------------
// Phase 1: pre = X @ Wx + bias. 128x128x8 register-tiled fp32 GEMM
// (R4 version, byte-for-byte). Block (0,0) resets phase-2 barrier state.
// ---------------------------------------------------------------------------
#define BM 128
#define BN 128
#define BK 8

__global__ __launch_bounds__(256) void gemm_pre_kernel(
    const float* __restrict__ X,
    const float* __restrict__ W,
    const float* __restrict__ bias)
{
    if (blockIdx.x == 0 && blockIdx.y == 0 && threadIdx.x < 4)
        g_grp[threadIdx.x * 16] = 0ULL;

    __shared__ float As[BK][BM];
    __shared__ float Bs[BK][BN];

    const int tid = threadIdx.x;
    const int bm = blockIdx.x;
    const int bn = blockIdx.y;

    const float* Aptr = X + (size_t)bm * BM * IN_DIM;
    const float* Bptr = W + (size_t)bn * BN;

    const int tm = (tid / 16) * 8;
    const int tn = (tid % 16) * 8;

    const int a_row = tid >> 1;
    const int a_kq  = (tid & 1) * 4;
    const int b_k   = tid >> 5;
    const int b_nq  = (tid & 31) * 4;

    float c[8][8];
    #pragma unroll
    for (int i = 0; i < 8; i++)
        #pragma unroll
        for (int j = 0; j < 8; j++)
            c[i][j] = 0.0f;

    for (int k0 = 0; k0 < IN_DIM; k0 += BK) {
        float4 av = *(const float4*)(Aptr + (size_t)a_row * IN_DIM + k0 + a_kq);
        float4 bv = *(const float4*)(Bptr + (size_t)(k0 + b_k) * RNN_DIM + b_nq);
        __syncthreads();
        As[a_kq + 0][a_row] = av.x;
        As[a_kq + 1][a_row] = av.y;
        As[a_kq + 2][a_row] = av.z;
        As[a_kq + 3][a_row] = av.w;
        *(float4*)&Bs[b_k][b_nq] = bv;
        __syncthreads();

        #pragma unroll
        for (int k = 0; k < BK; k++) {
            float ar[8], br[8];
            *(float4*)(ar)     = *(float4*)&As[k][tm];
            *(float4*)(ar + 4) = *(float4*)&As[k][tm + 4];
            *(float4*)(br)     = *(float4*)&Bs[k][tn];
            *(float4*)(br + 4) = *(float4*)&Bs[k][tn + 4];
            #pragma unroll
            for (int i = 0; i < 8; i++)
                #pragma unroll
                for (int j = 0; j < 8; j++)
                    c[i][j] += ar[i] * br[j];
        }
    }

    float4 bb0 = *(const float4*)(bias + bn * BN + tn);
    float4 bb1 = *(const float4*)(bias + bn * BN + tn + 4);
    #pragma unroll
    for (int i = 0; i < 8; i++) {
        size_t row = (size_t)bm * BM + tm + i;
        float4 v0, v1;
        v0.x = c[i][0] + bb0.x; v0.y = c[i][1] + bb0.y;
        v0.z = c[i][2] + bb0.z; v0.w = c[i][3] + bb0.w;
        v1.x = c[i][4] + bb1.x; v1.y = c[i][5] + bb1.y;
        v1.z = c[i][6] + bb1.z; v1.w = c[i][7] + bb1.w;
        *(float4*)(g_pre + row * RNN_DIM + bn * BN + tn)     = v0;
        *(float4*)(g_pre + row * RNN_DIM + bn * BN + tn + 4) = v1;
    }
}

// ---------------------------------------------------------------------------
// Phase 2: persistent RNN — R4 structure, plus:
//  - split arrive/wait barrier (out-store + pre-prefetch between them)
// ---------------------------------------------------------------------------
__device__ __forceinline__ void group_arrive(int grp)
{
    __syncthreads();                     // all g_hT stores issued
    if (threadIdx.x == 0) {
        __threadfence();
        atomicAdd(&g_grp[grp * 16], 1ULL);   // no-return -> REDG
    }
}
__device__ __forceinline__ void group_wait(int grp, ull step)
{
    if (threadIdx.x == 0) {
        volatile ull* ctr = (volatile ull*)&g_grp[grp * 16];
        ull need = (ull)GRP_SZ * step;
        while (*ctr < need) { }
        __threadfence();
    }
    __syncthreads();
}

extern __shared__ float smem2[];

__global__ __launch_bounds__(NTHR2) void rnn_seq_kernel(
    const float* __restrict__ W,
    const float* __restrict__ init_hidden,
    float* __restrict__ out)
{
    float* ws = smem2;                 // [512][16] Wh slice, 32KB
    float* hs = smem2 + RNN_DIM * 16;  // [512][16] h slab, 32KB (rows<256 = red)

    const int tid  = threadIdx.x;
    const int jblk = blockIdx.x & 31;
    const int bblk = blockIdx.x >> 5;
    const int j0 = jblk * 16;
    const int b0 = bblk * 16;

    // Wh slice (rows 512..1023 of W, cols j0..j0+15), loaded once
    #pragma unroll
    for (int i = 0; i < 8; i++) {
        int idx = tid + i * NTHR2;
        int r = idx >> 2, q = (idx & 3) * 4;
        *(float4*)&ws[r * 16 + q] =
            *(const float4*)(W + (size_t)(IN_DIM + r) * RNN_DIM + j0 + q);
    }

    // out[0] tile = broadcast init_hidden
    {
        int b = tid >> 4, j = tid & 15;
        out[(size_t)(b0 + b) * RNN_DIM + j0 + j] = init_hidden[j0 + j];
    }
    // g_hT[0][r][b0..b0+15] = init_hidden[r]  (one CTA per group: jblk==0)
    if (jblk == 0) {
        int kbase = (tid >> 2) * 8;
        int q = (tid & 3) * 4;
        #pragma unroll
        for (int kk = 0; kk < 8; kk++) {
            int k = kbase + kk;
            float v = init_hidden[k];
            *(float4*)&g_hT[0][k * BATCH + b0 + q] = make_float4(v, v, v, v);
        }
    }
    group_arrive(bblk);

    const int kg = tid >> 4;              // 0..15, k = kg + 16*kk (strided)
    const int tt = tid & 15;
    const int bq = (tt >> 2) * 4;         // 0,4,8,12
    const int jq = (tt & 3) * 4;          // 0,4,8,12
    const int fb = tid >> 4;              // epilogue b
    const int fj = tid & 15;              // epilogue j

    // prefetch pre[0] while waiting for h(0) publication
    float pre = g_pre[((size_t)0 * BATCH + b0 + fb) * RNN_DIM + j0 + fj];
    group_wait(bblk, 1ULL);

    for (int t = 0; t < T_STEPS - 1; t++) {
        const float* hsrc = g_hT[t & 1];

        // stage half0 (rows 0..255)
        float4 r0[4];
        #pragma unroll
        for (int i = 0; i < 4; i++) {
            int idx = tid + i * NTHR2;
            int r = idx >> 2, q = (idx & 3) * 4;
            r0[i] = *(const float4*)(hsrc + r * BATCH + b0 + q);
        }
        #pragma unroll
        for (int i = 0; i < 4; i++) {
            int idx = tid + i * NTHR2;
            int r = idx >> 2, q = (idx & 3) * 4;
            *(float4*)&hs[r * 16 + q] = r0[i];
        }
        __syncthreads();

        // issue half1 loads (rows 256..511), overlap with compute half0
        float4 r1[4];
        #pragma unroll
        for (int i = 0; i < 4; i++) {
            int idx = tid + (i + 4) * NTHR2;
            int r = idx >> 2, q = (idx & 3) * 4;
            r1[i] = *(const float4*)(hsrc + r * BATCH + b0 + q);
        }

        float c[4][4];
        #pragma unroll
        for (int i = 0; i < 4; i++)
            #pragma unroll
            for (int j = 0; j < 4; j++)
                c[i][j] = 0.0f;

        #pragma unroll 4
        for (int kk = 0; kk < 16; kk++) {       // k in [0,256)
            int k = kg + (kk << 4);
            float4 hv = *(float4*)&hs[k * 16 + bq];
            float4 wv = *(float4*)&ws[k * 16 + jq];
            c[0][0] += hv.x * wv.x; c[0][1] += hv.x * wv.y;
            c[0][2] += hv.x * wv.z; c[0][3] += hv.x * wv.w;
            c[1][0] += hv.y * wv.x; c[1][1] += hv.y * wv.y;
            c[1][2] += hv.y * wv.z; c[1][3] += hv.y * wv.w;
            c[2][0] += hv.z * wv.x; c[2][1] += hv.z * wv.y;
            c[2][2] += hv.z * wv.z; c[2][3] += hv.z * wv.w;
            c[3][0] += hv.w * wv.x; c[3][1] += hv.w * wv.y;
            c[3][2] += hv.w * wv.z; c[3][3] += hv.w * wv.w;
        }

        #pragma unroll
        for (int i = 0; i < 4; i++) {
            int idx = tid + (i + 4) * NTHR2;
            int r = idx >> 2, q = (idx & 3) * 4;
            *(float4*)&hs[r * 16 + q] = r1[i];
        }
        __syncthreads();

        #pragma unroll 4
        for (int kk = 16; kk < 32; kk++) {      // k in [256,512)
            int k = kg + (kk << 4);
            float4 hv = *(float4*)&hs[k * 16 + bq];
            float4 wv = *(float4*)&ws[k * 16 + jq];
            c[0][0] += hv.x * wv.x; c[0][1] += hv.x * wv.y;
            c[0][2] += hv.x * wv.z; c[0][3] += hv.x * wv.w;
            c[1][0] += hv.y * wv.x; c[1][1] += hv.y * wv.y;
            c[1][2] += hv.y * wv.z; c[1][3] += hv.y * wv.w;
            c[2][0] += hv.z * wv.x; c[2][1] += hv.z * wv.y;
            c[2][2] += hv.z * wv.z; c[2][3] += hv.z * wv.w;
            c[3][0] += hv.w * wv.x; c[3][1] += hv.w * wv.y;
            c[3][2] += hv.w * wv.z; c[3][3] += hv.w * wv.w;
        }

        // k-split partials overlay hs rows < 256 (safe: half1 reads rows >= 256)
        float* red = hs;
        #pragma unroll
        for (int i = 0; i < 4; i++)
            #pragma unroll
            for (int j = 0; j < 4; j++)
                red[kg * 256 + (bq + i) * 16 + (jq + j)] = c[i][j];
        __syncthreads();

        float s = 0.0f;
        #pragma unroll
        for (int g = 0; g < 16; g++)
            s += red[g * 256 + tid];            // tid == b*16+j, conflict-free
        float h = tanhf(s + pre);
        g_hT[(t + 1) & 1][(j0 + fj) * BATCH + b0 + fb] = h;

        if (t < T_STEPS - 2) {
            group_arrive(bblk);                 // publish ASAP
            // off-critical-path work under the barrier wait:
            out[((size_t)(t + 1) * BATCH + b0 + fb) * RNN_DIM + j0 + fj] = h;
            pre = g_pre[((size_t)(t + 1) * BATCH + b0 + fb) * RNN_DIM + j0 + fj];
            group_wait(bblk, (ull)(t + 2));
        } else {
            out[((size_t)(t + 1) * BATCH + b0 + fb) * RNN_DIM + j0 + fj] = h;
        }
    }
}

// ---------------------------------------------------------------------------
extern "C" void kernel_launch(void* const* d_in, const int* in_sizes, int n_in,
                              void* d_out, int out_size)
{
    const float* X    = (const float*)d_in[0];  // [T, B, IN_DIM]
    const float* W    = (const float*)d_in[1];  // [IN_DIM + RNN_DIM, RNN_DIM]
    const float* bias = (const float*)d_in[2];  // [RNN_DIM]
    const float* h0   = (const float*)d_in[3];  // [RNN_DIM]
    float* out = (float*)d_out;                 // [T, B, RNN_DIM]

    cudaFuncSetAttribute(rnn_seq_kernel,
                         cudaFuncAttributeMaxDynamicSharedMemorySize, 65536);

    dim3 g1((T_STEPS * BATCH) / BM, RNN_DIM / BN);  // (256, 4)
    gemm_pre_kernel<<<g1, 256>>>(X, W, bias);

    rnn_seq_kernel<<<NCTA2, NTHR2, 65536>>>(W, h0, out);
}